// round 5
// baseline (speedup 1.0000x reference)
#include <cuda_runtime.h>

#define N_CELLS 100000
#define N_ISO   16
#define KP1     31
#define WARPS_PER_BLOCK 8
#define THREADS (WARPS_PER_BLOCK * 32)
#define GRID    888                      /* 148 SMs x 6 blocks/SM -> one resident wave */
#define TOTAL_WARPS (GRID * WARPS_PER_BLOCK)
#define ROWF    32                       /* packed row stride in floats (128B) */
#define LIVEF   20                       /* floats actually written per row */

__device__ float        g_packS[(size_t)N_CELLS * ROWF];
__device__ float        g_packP[(size_t)N_CELLS * ROWF];
__device__ float        g_partials[GRID];
__device__ unsigned int g_ticket = 0;

// Pack [u, s0..s15, 0,0,0] per cell into 128B-aligned rows (and same for up/sp).
// One thread per live float; coalesced-ish reads and writes.
__global__ void pack_kernel(const float* __restrict__ u,
                            const float* __restrict__ s,
                            const float* __restrict__ up,
                            const float* __restrict__ sp)
{
    const int t = blockIdx.x * blockDim.x + threadIdx.x;
    if (t >= N_CELLS * LIVEF) return;
    const int cell = t / LIVEF;
    const int m    = t - cell * LIVEF;

    float vs = 0.0f, vp = 0.0f;
    if (m == 0)       { vs = u[cell];                    vp = up[cell]; }
    else if (m <= 16) { vs = s[(size_t)cell * N_ISO + m - 1];
                        vp = sp[(size_t)cell * N_ISO + m - 1]; }
    const size_t o = (size_t)cell * ROWF + m;
    g_packS[o] = vs;
    g_packP[o] = vp;
}

__global__ __launch_bounds__(THREADS, 6) void cost_kernel(
    const int* __restrict__ idx,
    float* __restrict__ out)
{
    const int warp  = threadIdx.x >> 5;
    const int lane  = threadIdx.x & 31;
    const int gwarp = blockIdx.x * WARPS_PER_BLOCK + warp;
    const int r     = lane & 7;          // slice index within an 8-lane group
    const int g     = lane >> 3;         // group (= neighbor sub-slot) 0..3

    __shared__ float ws[WARPS_PER_BLOCK];
    __shared__ int   s_islast;

    float lsum = 0.0f;

    for (int cell = gwarp; cell < N_CELLS; cell += TOTAL_WARPS) {
        // Own packed row slices (same row for all groups -> 1 wavefront, broadcast).
        float4 a = make_float4(0.f, 0.f, 0.f, 0.f);
        float4 b = a;
        if (r < 5) {
            a = *reinterpret_cast<const float4*>(g_packS + (size_t)cell * ROWF + 4 * r);
            b = *reinterpret_cast<const float4*>(g_packP + (size_t)cell * ROWF + 4 * r);
        }
        // v slice (r=0 lane's .x is uv; r>=5 lanes are all-zero).
        const float sv0 = b.x - a.x, sv1 = b.y - a.y, sv2 = b.z - a.z, sv3 = b.w - a.w;

        float pv = sv0*sv0 + sv1*sv1 + sv2*sv2 + sv3*sv3;
        pv += __shfl_xor_sync(0xffffffffu, pv, 1);
        pv += __shfl_xor_sync(0xffffffffu, pv, 2);
        pv += __shfl_xor_sync(0xffffffffu, pv, 4);
        const float vsq = pv;            // |v|^2, identical across the warp

        // Coalesced neighbor indices: lanes 0..29.
        int my_idx = 0;
        if (lane < KP1 - 1) my_idx = idx[(size_t)cell * KP1 + 1 + lane];

        float cmax = -3.0e38f;

        #pragma unroll
        for (int bt = 0; bt < 8; bt++) {
            const int slot = bt * 4 + g;                            // neighbor 0..31
            const int j    = __shfl_sync(0xffffffffu, my_idx, slot);

            // 4 neighbors per LDG, each row = ONE 128B line (u folded in).
            float4 nr = make_float4(0.f, 0.f, 0.f, 0.f);
            if (r < 5)
                nr = *reinterpret_cast<const float4*>(g_packS + (size_t)j * ROWF + 4 * r);

            const float d0 = nr.x - a.x, d1 = nr.y - a.y, d2 = nr.z - a.z, d3 = nr.w - a.w;

            float pdot = sv0*d0 + sv1*d1 + sv2*d2 + sv3*d3;
            float pnsq = d0*d0 + d1*d1 + d2*d2 + d3*d3;

            pdot += __shfl_xor_sync(0xffffffffu, pdot, 1);
            pdot += __shfl_xor_sync(0xffffffffu, pdot, 2);
            pdot += __shfl_xor_sync(0xffffffffu, pdot, 4);
            pnsq += __shfl_xor_sync(0xffffffffu, pnsq, 1);
            pnsq += __shfl_xor_sync(0xffffffffu, pnsq, 2);
            pnsq += __shfl_xor_sync(0xffffffffu, pnsq, 4);

            if (r == 0 && slot < KP1 - 1) {
                const float den2 = vsq * pnsq;
                const float cosv = (den2 > 0.0f) ? pdot * rsqrtf(den2) : pdot;
                cmax = fmaxf(cmax, cosv);
            }
        }

        // Warp max over the group leaders (others hold the sentinel).
        #pragma unroll
        for (int o = 16; o > 0; o >>= 1)
            cmax = fmaxf(cmax, __shfl_xor_sync(0xffffffffu, cmax, o));

        if (lane == 0) lsum += 1.0f - cmax;
    }

    if (lane == 0) ws[warp] = lsum;
    __syncthreads();

    if (threadIdx.x == 0) {
        float bsum = 0.0f;
        #pragma unroll
        for (int w = 0; w < WARPS_PER_BLOCK; w++) bsum += ws[w];
        g_partials[blockIdx.x] = bsum;
        __threadfence();
        const unsigned t = atomicInc(&g_ticket, GRID - 1);  // wraps -> graph-replay safe
        s_islast = (t == GRID - 1);
    }
    __syncthreads();

    if (s_islast) {
        float psum = 0.0f;
        const volatile float* vp = g_partials;
        for (int i = threadIdx.x; i < GRID; i += THREADS) psum += vp[i];
        #pragma unroll
        for (int o = 16; o > 0; o >>= 1)
            psum += __shfl_xor_sync(0xffffffffu, psum, o);
        if (lane == 0) ws[warp] = psum;
        __syncthreads();
        if (threadIdx.x == 0) {
            float total = 0.0f;
            #pragma unroll
            for (int w = 0; w < WARPS_PER_BLOCK; w++) total += ws[w];
            out[0] = total * (1.0f / (float)N_CELLS);
        }
    }
}

extern "C" void kernel_launch(void* const* d_in, const int* in_sizes, int n_in,
                              void* d_out, int out_size) {
    const float* u   = (const float*)d_in[0];
    const float* s   = (const float*)d_in[1];
    const float* up  = (const float*)d_in[2];
    const float* sp  = (const float*)d_in[3];
    const int*   idx = (const int*)d_in[4];
    float* out = (float*)d_out;

    const int pack_grid = (N_CELLS * LIVEF + 255) / 256;
    pack_kernel<<<pack_grid, 256>>>(u, s, up, sp);
    cost_kernel<<<GRID, THREADS>>>(idx, out);
}